// round 15
// baseline (speedup 1.0000x reference)
#include <cuda_runtime.h>
#include <stdint.h>

// ---------------- problem constants ----------------
#define T_STEPS 16
#define NNODES  50000
#define IN_F    128
#define B_N     4096
#define S1_N    5
#define S2_N    2
#define H1_N    128
#define H2_N    64
#define C_OUT   32
#define K_CONV  5
#define R1      (B_N + B_N * S1_N)   // 24576 layer-1 rows per timestep
#define KTOT    256                  // layer-1 K ([self 128 | neigh 128])
#define NBLK    (R1 / 128)           // 192 layer-1 CTAs per timestep
#define APAD    44                   // smem row stride (floats): 16B-aligned, conflict-free
#define BUFF    (2 * 128 * APAD)     // one (Ah,Bh) buffer in floats
#define EPS_RESCUE 3e-3f             // |u-thr| window recomputed in exact fp32

typedef unsigned long long ull;

// ---------------- scratch (static device memory; no allocations) ----------------
__device__ uint8_t g_s1[(size_t)T_STEPS * R1 * H1_N];     // ~50 MB layer-1 spikes
__device__ uint8_t g_s2[(size_t)T_STEPS * B_N * H2_N];    // ~4 MB  layer-2 spikes
__device__ float   g_A[H2_N * T_STEPS];                   // folded delay+conv weights
__device__ float   g_W1hi[H1_N * KTOT];                   // W1^T [n][k], tf32-rna rounded
__device__ float   g_W1T [H1_N * KTOT];                   // W1^T [n][k], exact fp32 (rescue)
__device__ float   g_Aex[(size_t)T_STEPS * NBLK * 128 * KTOT];  // exact A panels (~403 MB)

// ---------------- helpers ----------------
__device__ __forceinline__ float tf32r(float x) {
    uint32_t u;
    asm("cvt.rna.tf32.f32 %0, %1;" : "=r"(u) : "f"(x));
    return __uint_as_float(u);
}

#define MMA_TF32(d, a, b0, b1)                                            \
    asm volatile("mma.sync.aligned.m16n8k8.row.col.f32.tf32.tf32.f32 "    \
                 "{%0,%1,%2,%3}, {%4,%5,%6,%7}, {%8,%9}, {%0,%1,%2,%3};"  \
                 : "+f"((d)[0]), "+f"((d)[1]), "+f"((d)[2]), "+f"((d)[3]) \
                 : "r"((a)[0]), "r"((a)[1]), "r"((a)[2]), "r"((a)[3]),    \
                   "r"(b0), "r"(b1))

__device__ __forceinline__ ull fma2(ull a, ull b, ull c) {
    ull d;
    asm("fma.rn.f32x2 %0, %1, %2, %3;" : "=l"(d) : "l"(a), "l"(b), "l"(c));
    return d;
}
__device__ __forceinline__ ull dup2(float v) {
    ull r;
    asm("mov.b64 %0, {%1, %1};" : "=l"(r) : "f"(v));
    return r;
}
__device__ __forceinline__ float lo2(ull v) { return __uint_as_float((unsigned)(v)); }
__device__ __forceinline__ float hi2(ull v) { return __uint_as_float((unsigned)(v >> 32)); }

// ---------------- exact fp32 rescue: contiguous dot over spilled exact A ------
// Single accumulator, k ascending over [self(128) | neigh_mean(128)] — the
// SAME arithmetic sequence as the validated round-13/14 rescue (bitwise equal).
__device__ __noinline__ bool rescue_dot(const float* __restrict__ arow,
                                        const float* __restrict__ wr, float thr) {
    float u = 0.0f;
    #pragma unroll 8
    for (int k = 0; k < KTOT; k++)
        u = fmaf(arow[k], wr[k], u);
    return u >= thr;
}

// ============================================================================
// Kernel 0a: fold softmax(delay_w) + depthwise-conv SAME + time-mean into A[c][t].
// ============================================================================
__global__ void prepA_kernel(const float* __restrict__ delay_w,
                             const float* __restrict__ dwk) {
    int c = threadIdx.x;
    if (c >= H2_N) return;
    int g = c >> 3;
    float w0 = delay_w[g * 3 + 0], w1 = delay_w[g * 3 + 1], w2 = delay_w[g * 3 + 2];
    float mx = fmaxf(w0, fmaxf(w1, w2));
    float e0 = expf(w0 - mx), e1 = expf(w1 - mx), e2 = expf(w2 - mx);
    float inv = 1.0f / (e0 + e1 + e2);
    e0 *= inv; e1 *= inv; e2 *= inv;

    float coef[T_STEPS];
    #pragma unroll
    for (int tau = 0; tau < T_STEPS; tau++) {
        int kmin = (tau - 13 > 0) ? (tau - 13) : 0;
        int kmax = (tau + 2 < 4) ? (tau + 2) : 4;
        float s = 0.0f;
        for (int k = kmin; k <= kmax; k++) s += dwk[c * K_CONV + k];
        coef[tau] = s * (1.0f / (float)T_STEPS);
    }
    #pragma unroll
    for (int t = 0; t < T_STEPS; t++) {
        float a = 0.0f;
        if (t + 1 < T_STEPS) a += e0 * coef[t + 1];
        if (t + 3 < T_STEPS) a += e1 * coef[t + 3];
        if (t + 5 < T_STEPS) a += e2 * coef[t + 5];
        g_A[c * T_STEPS + t] = a;
    }
}

// ============================================================================
// Kernel 0b: transpose W1 into [n][k]: tf32-rna copy (MMA) + exact copy (rescue).
// ============================================================================
__global__ void prepW1_kernel(const float* __restrict__ W1s,
                              const float* __restrict__ W1n) {
    int idx = blockIdx.x * 256 + threadIdx.x;   // 32768 total
    int n = idx & (H1_N - 1);
    int k = idx >> 7;
    float w = (k < IN_F) ? W1s[(size_t)k * H1_N + n]
                         : W1n[(size_t)(k - IN_F) * H1_N + n];
    g_W1hi[n * KTOT + k] = tf32r(w);
    g_W1T [n * KTOT + k] = w;
}

// ============================================================================
// Kernel 1a: GATHER — scattered loads + neighbor mean -> exact A panels (g_Aex).
// No smem tiles, no accumul tile: low regs, full occupancy, latency-tolerant.
// Arithmetic identical to the fused R13/R14 gather (bitwise).
// ============================================================================
__global__ void __launch_bounds__(256)
gather_kernel(const float* __restrict__ x, const int* __restrict__ nodes,
              const int* __restrict__ nbr1, const int* __restrict__ nbr2) {
    __shared__ int s_self[128];
    __shared__ int s_nbr[128 * S1_N];

    const int tid = threadIdx.x;
    const int t = blockIdx.y;
    const int blk = blockIdx.x;               // 0..191
    const int typeA = (blk < (B_N / 128));
    const int rowbase = blk * 128;
    const size_t aex = ((size_t)t * NBLK + blk) * (128 * KTOT);

    if (typeA) {
        if (tid < 128) s_self[tid] = nodes[rowbase + tid];
        for (int q = tid; q < 128 * S1_N; q += 256) {
            int r = q / S1_N, s = q - r * S1_N;
            s_nbr[q] = nbr1[((size_t)t * B_N + rowbase + r) * S1_N + s];
        }
    } else {
        const int j0 = rowbase - B_N;
        if (tid < 128) s_self[tid] = nbr1[(size_t)t * B_N * S1_N + j0 + tid];
        for (int q = tid; q < 128 * S2_N; q += 256) {
            int r = q >> 1, s = q & 1;
            s_nbr[q] = nbr2[((size_t)t * (B_N * S1_N) + j0 + r) * S2_N + s];
        }
    }
    __syncthreads();

    const float* xt = x + (size_t)t * NNODES * IN_F;
    const int gr = tid >> 1;                  // row 0..127
    const int gq = (tid & 1) * 4;             // first of 4 float4 quads per 32-chunk
    float* arow = g_Aex + aex + (size_t)gr * KTOT;

    // self features: k [0,128)
    {
        const float* src = xt + (size_t)s_self[gr] * IN_F;
        #pragma unroll
        for (int kc = 0; kc < 4; kc++) {
            #pragma unroll
            for (int i = 0; i < 4; i++) {
                int f = kc * 32 + (gq + i) * 4;
                float4 v = *(const float4*)(src + f);
                __stcs((float4*)(arow + f), v);
            }
        }
    }
    // neighbor-mean features: k [128,256)
    const int   S    = typeA ? S1_N : S2_N;
    const float invS = typeA ? 0.2f : 0.5f;
    #pragma unroll
    for (int kc = 0; kc < 4; kc++) {
        #pragma unroll
        for (int i = 0; i < 4; i++) {
            int f = kc * 32 + (gq + i) * 4;
            float ax = 0.f, ay = 0.f, az = 0.f, aw = 0.f;
            for (int s = 0; s < S; s++) {
                float4 v = *(const float4*)(xt + (size_t)s_nbr[gr * S + s] * IN_F + f);
                ax += v.x; ay += v.y; az += v.z; aw += v.w;
            }
            __stcs((float4*)(arow + IN_F + f),
                   make_float4(ax * invS, ay * invS, az * invS, aw * invS));
        }
    }
}

// ============================================================================
// Kernel 1b: GEMM — dense pipelined single-pass tf32 mma.sync over g_Aex + spike.
// A loads are contiguous streams (tf32-round during smem staging); double-
// buffered smem hides them under MMAs. Rescue identical (exact fp32 over Aex).
// ============================================================================
__global__ void __launch_bounds__(256, 2)
gemm_kernel(const float* __restrict__ b1) {
    extern __shared__ float sm[];
    __shared__ float s_thr[128];

    const int tid = threadIdx.x;
    const int wid = tid >> 5;
    const int lane = tid & 31;
    const int t = blockIdx.y;
    const int blk = blockIdx.x;               // 0..191
    const int rowbase = blk * 128;
    const size_t aex = ((size_t)t * NBLK + blk) * (128 * KTOT);

    if (tid < 128) s_thr[tid] = 1.0f - b1[tid];

    const int gr = tid >> 1;                  // row / n index 0..127
    const int gq = (tid & 1) * 4;             // first of 4 float4 quads

    // warp tile 32x64: 4 M-groups x 2 N-groups
    const int mbase = (wid & 3) * 32;
    const int nbase = (wid >> 2) * 64;
    const int g  = lane >> 2;                 // 0..7
    const int tg = lane & 3;                  // 0..3

    float acc[2][8][4];
    #pragma unroll
    for (int mt = 0; mt < 2; mt++)
        #pragma unroll
        for (int j = 0; j < 8; j++)
            #pragma unroll
            for (int c = 0; c < 4; c++) acc[mt][j][c] = 0.0f;

    float4 av[4];    // exact A values for staged chunk
    float4 bv[4];    // tf32-pre-rounded B values for staged chunk

    auto load_chunk = [&](int kc) {
        const float* sa = g_Aex + aex + (size_t)gr * KTOT + kc * 32;
        const float* sh = g_W1hi + (size_t)gr * KTOT + kc * 32;
        #pragma unroll
        for (int i = 0; i < 4; i++) {
            av[i] = *(const float4*)(sa + (gq + i) * 4);
            bv[i] = *(const float4*)(sh + (gq + i) * 4);
        }
    };
    auto store_chunk = [&](int b) {
        float* Ah = sm + b * BUFF;
        float* Bh = Ah + 128 * APAD;
        #pragma unroll
        for (int i = 0; i < 4; i++) {
            int o = gr * APAD + (gq + i) * 4;
            *(float4*)(Ah + o) = make_float4(tf32r(av[i].x), tf32r(av[i].y),
                                             tf32r(av[i].z), tf32r(av[i].w));
            *(float4*)(Bh + o) = bv[i];
        }
    };

    load_chunk(0);
    store_chunk(0);

    for (int kc = 0; kc < 8; kc++) {
        __syncthreads();   // buffer (kc&1) visible
        if (kc < 7) load_chunk(kc + 1);       // dense LDGs in flight during MMAs

        const uint32_t* Ah_u = (const uint32_t*)(sm + (kc & 1) * BUFF);
        const uint32_t* Bh_u = Ah_u + 128 * APAD;
        #pragma unroll
        for (int k8 = 0; k8 < 4; k8++) {
            const int kb = k8 * 8;
            uint32_t ah[2][4];
            #pragma unroll
            for (int mt = 0; mt < 2; mt++) {
                int r0 = (mbase + 16 * mt + g) * APAD + kb + tg;
                int r8 = r0 + 8 * APAD;
                ah[mt][0] = Ah_u[r0];     ah[mt][1] = Ah_u[r8];
                ah[mt][2] = Ah_u[r0 + 4]; ah[mt][3] = Ah_u[r8 + 4];
            }
            #pragma unroll
            for (int j = 0; j < 8; j++) {
                int bi = (nbase + 8 * j + g) * APAD + kb + tg;
                uint32_t bh0 = Bh_u[bi], bh1 = Bh_u[bi + 4];
                MMA_TF32(acc[0][j], ah[0], bh0, bh1);
                MMA_TF32(acc[1][j], ah[1], bh0, bh1);
            }
        }

        if (kc < 7) store_chunk((kc + 1) & 1);
    }

    // ---- epilogue: threshold (+ exact rescue) -> byte-stage -> coalesced store ----
    __syncthreads();
    uint8_t* sbytes = (uint8_t*)sm;           // reuse buffer-0 Ah region (16 KB)
    #pragma unroll
    for (int mt = 0; mt < 2; mt++) {
        int R0 = mbase + 16 * mt + g;
        #pragma unroll
        for (int j = 0; j < 8; j++) {
            int C0 = nbase + 8 * j + 2 * tg;
            #pragma unroll
            for (int c = 0; c < 4; c++) {
                int R = R0 + (c >> 1) * 8;
                int C = C0 + (c & 1);
                float thr = s_thr[C];
                float d = acc[mt][j][c] - thr;
                bool sp;
                if (fabsf(d) < EPS_RESCUE) {
                    sp = rescue_dot(g_Aex + aex + (size_t)R * KTOT,
                                    g_W1T + (size_t)C * KTOT, thr);
                } else {
                    sp = (d >= 0.0f);
                }
                sbytes[R * 128 + C] = sp ? 1 : 0;
            }
        }
    }
    __syncthreads();
    uint8_t* dst = g_s1 + ((size_t)t * R1 + rowbase) * H1_N;
    #pragma unroll
    for (int i = 0; i < 4; i++) {
        int o = (tid + i * 256) * 16;
        *(uint4*)(dst + o) = *(const uint4*)(sbytes + o);
    }
}

// ============================================================================
// Kernel 2: layer-2 GEMM, packed fp32x2, W streamed from L1 (no smem staging).
// ============================================================================
__global__ void __launch_bounds__(256, 2)
layer2_kernel(const float* __restrict__ W2s, const float* __restrict__ W2n,
              const float* __restrict__ b2) {
    extern __shared__ float sm[];
    float* Zt = sm;                  // [256][64] k-major
    const int tid = threadIdx.x;
    const int t = blockIdx.y;
    const int b0 = blockIdx.x * 64;

    const uint8_t* s1t = g_s1 + (size_t)t * R1 * H1_N;
    const int r  = tid & 63;
    const int w0 = tid >> 6;
    for (int w = w0; w < 32; w += 4) {
        uint32_t gw = *(const uint32_t*)(s1t + (size_t)(b0 + r) * H1_N + w * 4);
        uint32_t mw = 0;   // bytes are 0/1; sum of 5 fits in a byte
        #pragma unroll
        for (int s = 0; s < S1_N; s++)
            mw += *(const uint32_t*)(s1t + (size_t)(B_N + (b0 + r) * S1_N + s) * H1_N + w * 4);
        int k = w * 4;
        Zt[(k + 0) * 64 + r] = (float)(gw & 0xffu);
        Zt[(k + 1) * 64 + r] = (float)((gw >> 8) & 0xffu);
        Zt[(k + 2) * 64 + r] = (float)((gw >> 16) & 0xffu);
        Zt[(k + 3) * 64 + r] = (float)(gw >> 24);
        Zt[(H1_N + k + 0) * 64 + r] = 0.2f * (float)(mw & 0xffu);
        Zt[(H1_N + k + 1) * 64 + r] = 0.2f * (float)((mw >> 8) & 0xffu);
        Zt[(H1_N + k + 2) * 64 + r] = 0.2f * (float)((mw >> 16) & 0xffu);
        Zt[(H1_N + k + 3) * 64 + r] = 0.2f * (float)(mw >> 24);
    }
    __syncthreads();

    const int r0 = (tid & 15) * 4;
    const int c0 = (tid >> 4) * 4;

    ull acc[2][4];
    #pragma unroll
    for (int i = 0; i < 2; i++)
        #pragma unroll
        for (int j = 0; j < 4; j++) acc[i][j] = 0ull;

    // k in [0,128): W2s ; k in [128,256): W2n — same order (bit-identical spikes)
    #pragma unroll
    for (int h = 0; h < 2; h++) {
        const float* Wp = h ? W2n : W2s;
        const int kofs = h * H1_N;
        #pragma unroll 8
        for (int k = 0; k < 128; k++) {
            const ull* za = (const ull*)&Zt[(kofs + k) * 64 + r0];
            ull a0 = za[0], a1 = za[1];
            float4 b4 = *(const float4*)(Wp + (size_t)k * H2_N + c0);
            ull bd0 = dup2(b4.x), bd1 = dup2(b4.y), bd2 = dup2(b4.z), bd3 = dup2(b4.w);
            acc[0][0] = fma2(a0, bd0, acc[0][0]);
            acc[1][0] = fma2(a1, bd0, acc[1][0]);
            acc[0][1] = fma2(a0, bd1, acc[0][1]);
            acc[1][1] = fma2(a1, bd1, acc[1][1]);
            acc[0][2] = fma2(a0, bd2, acc[0][2]);
            acc[1][2] = fma2(a1, bd2, acc[1][2]);
            acc[0][3] = fma2(a0, bd3, acc[0][3]);
            acc[1][3] = fma2(a1, bd3, acc[1][3]);
        }
    }

    float bb[4];
    #pragma unroll
    for (int j = 0; j < 4; j++) bb[j] = b2[c0 + j];
    #pragma unroll
    for (int i = 0; i < 2; i++) {
        int b = b0 + r0 + 2 * i;
        uint32_t pk0 = 0, pk1 = 0;
        #pragma unroll
        for (int j = 0; j < 4; j++) {
            if (lo2(acc[i][j]) + bb[j] >= 1.0f) pk0 |= (1u << (8 * j));
            if (hi2(acc[i][j]) + bb[j] >= 1.0f) pk1 |= (1u << (8 * j));
        }
        *(uint32_t*)(g_s2 + ((size_t)t * B_N + b)     * H2_N + c0) = pk0;
        *(uint32_t*)(g_s2 + ((size_t)t * B_N + b + 1) * H2_N + c0) = pk1;
    }
}

// ============================================================================
// Kernel 3: readout. out[b,j] = ro_b[j] + sum_c (sum_t s2[t,b,c]*A[c,t]) ro_W[c,j]
// ============================================================================
__global__ void __launch_bounds__(256)
readout_kernel(const float* __restrict__ ro_W, const float* __restrict__ ro_b,
               float* __restrict__ out) {
    __shared__ float Msm[8][64];
    const int warp = threadIdx.x >> 5;
    const int lane = threadIdx.x & 31;
    const int b = blockIdx.x * 8 + warp;

    float m0 = 0.f, m1 = 0.f;
    #pragma unroll
    for (int t = 0; t < T_STEPS; t++) {
        const uint8_t* row = g_s2 + ((size_t)t * B_N + b) * H2_N;
        m0 = fmaf((float)row[lane],      g_A[lane * T_STEPS + t],        m0);
        m1 = fmaf((float)row[lane + 32], g_A[(lane + 32) * T_STEPS + t], m1);
    }
    Msm[warp][lane] = m0;
    Msm[warp][lane + 32] = m1;
    __syncwarp();

    float o = ro_b[lane];
    #pragma unroll
    for (int c = 0; c < 64; c++)
        o = fmaf(Msm[warp][c], ro_W[c * C_OUT + lane], o);
    out[(size_t)b * C_OUT + lane] = o;
}

// ============================================================================
extern "C" void kernel_launch(void* const* d_in, const int* in_sizes, int n_in,
                              void* d_out, int out_size) {
    const float* x    = (const float*)d_in[0];
    const int*   nodes= (const int*)  d_in[1];
    const int*   nbr1 = (const int*)  d_in[2];
    const int*   nbr2 = (const int*)  d_in[3];
    const float* W1s  = (const float*)d_in[4];
    const float* W1n  = (const float*)d_in[5];
    const float* b1   = (const float*)d_in[6];
    const float* W2s  = (const float*)d_in[7];
    const float* W2n  = (const float*)d_in[8];
    const float* b2   = (const float*)d_in[9];
    const float* dlw  = (const float*)d_in[10];
    const float* dwk  = (const float*)d_in[11];
    const float* roW  = (const float*)d_in[12];
    const float* rob  = (const float*)d_in[13];
    float* out = (float*)d_out;

    const int l1_smem = 2 * BUFF * 4;   // 90112 B (double-buffered)
    cudaFuncSetAttribute(gemm_kernel, cudaFuncAttributeMaxDynamicSharedMemorySize, l1_smem);
    cudaFuncSetAttribute(layer2_kernel, cudaFuncAttributeMaxDynamicSharedMemorySize, 65536);

    prepA_kernel<<<1, 64>>>(dlw, dwk);
    prepW1_kernel<<<128, 256>>>(W1s, W1n);
    gather_kernel<<<dim3(NBLK, T_STEPS), 256>>>(x, nodes, nbr1, nbr2);
    gemm_kernel<<<dim3(NBLK, T_STEPS), 256, l1_smem>>>(b1);
    layer2_kernel<<<dim3(B_N / 64, T_STEPS), 256, 65536>>>(W2s, W2n, b2);
    readout_kernel<<<B_N / 8, 256>>>(roW, rob, out);
}

// round 16
// speedup vs baseline: 1.0731x; 1.0731x over previous
#include <cuda_runtime.h>
#include <stdint.h>

// ---------------- problem constants ----------------
#define T_STEPS 16
#define NNODES  50000
#define IN_F    128
#define B_N     4096
#define S1_N    5
#define S2_N    2
#define H1_N    128
#define H2_N    64
#define C_OUT   32
#define K_CONV  5
#define R1      (B_N + B_N * S1_N)   // 24576 layer-1 rows per timestep
#define KTOT    256                  // layer-1 K ([self 128 | neigh 128])
#define NBLK    (R1 / 128)           // 192 layer-1 CTAs per timestep
#define APAD    44                   // smem row stride (floats): 16B-aligned, conflict-free
#define BUFF    (2 * 128 * APAD)     // one (Ah,Bh) buffer in floats
#define EPS_RESCUE 3e-3f             // |u-thr| window recomputed in exact fp32

typedef unsigned long long ull;

// ---------------- scratch (static device memory; no allocations) ----------------
__device__ uint8_t g_s1[(size_t)T_STEPS * R1 * H1_N];     // ~50 MB layer-1 spikes
__device__ uint8_t g_s2[(size_t)T_STEPS * B_N * H2_N];    // ~4 MB  layer-2 spikes
__device__ float   g_A[H2_N * T_STEPS];                   // folded delay+conv weights
__device__ float   g_W1hi[H1_N * KTOT];                   // W1^T [n][k], tf32-rna rounded
__device__ float   g_W1T [H1_N * KTOT];                   // W1^T [n][k], exact fp32 (rescue)
__device__ float   g_Aex[(size_t)T_STEPS * NBLK * 128 * KTOT];  // exact A panels (~403 MB)

// ---------------- helpers ----------------
__device__ __forceinline__ float tf32r(float x) {
    uint32_t u;
    asm("cvt.rna.tf32.f32 %0, %1;" : "=r"(u) : "f"(x));
    return __uint_as_float(u);
}

#define MMA_TF32(d, a, b0, b1)                                            \
    asm volatile("mma.sync.aligned.m16n8k8.row.col.f32.tf32.tf32.f32 "    \
                 "{%0,%1,%2,%3}, {%4,%5,%6,%7}, {%8,%9}, {%0,%1,%2,%3};"  \
                 : "+f"((d)[0]), "+f"((d)[1]), "+f"((d)[2]), "+f"((d)[3]) \
                 : "r"((a)[0]), "r"((a)[1]), "r"((a)[2]), "r"((a)[3]),    \
                   "r"(b0), "r"(b1))

__device__ __forceinline__ ull fma2(ull a, ull b, ull c) {
    ull d;
    asm("fma.rn.f32x2 %0, %1, %2, %3;" : "=l"(d) : "l"(a), "l"(b), "l"(c));
    return d;
}
__device__ __forceinline__ ull dup2(float v) {
    ull r;
    asm("mov.b64 %0, {%1, %1};" : "=l"(r) : "f"(v));
    return r;
}
__device__ __forceinline__ float lo2(ull v) { return __uint_as_float((unsigned)(v)); }
__device__ __forceinline__ float hi2(ull v) { return __uint_as_float((unsigned)(v >> 32)); }

// ---------------- exact fp32 rescue: contiguous dot over spilled exact A ------
// Single accumulator, k ascending over [self(128) | neigh_mean(128)] — the
// SAME arithmetic sequence as the validated round-13/14/15 rescue (bitwise equal).
__device__ __noinline__ bool rescue_dot(const float* __restrict__ arow,
                                        const float* __restrict__ wr, float thr) {
    float u = 0.0f;
    #pragma unroll 8
    for (int k = 0; k < KTOT; k++)
        u = fmaf(arow[k], wr[k], u);
    return u >= thr;
}

// ============================================================================
// Kernel 0a: fold softmax(delay_w) + depthwise-conv SAME + time-mean into A[c][t].
// ============================================================================
__global__ void prepA_kernel(const float* __restrict__ delay_w,
                             const float* __restrict__ dwk) {
    int c = threadIdx.x;
    if (c >= H2_N) return;
    int g = c >> 3;
    float w0 = delay_w[g * 3 + 0], w1 = delay_w[g * 3 + 1], w2 = delay_w[g * 3 + 2];
    float mx = fmaxf(w0, fmaxf(w1, w2));
    float e0 = expf(w0 - mx), e1 = expf(w1 - mx), e2 = expf(w2 - mx);
    float inv = 1.0f / (e0 + e1 + e2);
    e0 *= inv; e1 *= inv; e2 *= inv;

    float coef[T_STEPS];
    #pragma unroll
    for (int tau = 0; tau < T_STEPS; tau++) {
        int kmin = (tau - 13 > 0) ? (tau - 13) : 0;
        int kmax = (tau + 2 < 4) ? (tau + 2) : 4;
        float s = 0.0f;
        for (int k = kmin; k <= kmax; k++) s += dwk[c * K_CONV + k];
        coef[tau] = s * (1.0f / (float)T_STEPS);
    }
    #pragma unroll
    for (int t = 0; t < T_STEPS; t++) {
        float a = 0.0f;
        if (t + 1 < T_STEPS) a += e0 * coef[t + 1];
        if (t + 3 < T_STEPS) a += e1 * coef[t + 3];
        if (t + 5 < T_STEPS) a += e2 * coef[t + 5];
        g_A[c * T_STEPS + t] = a;
    }
}

// ============================================================================
// Kernel 0b: transpose W1 into [n][k]: tf32-rna copy (MMA) + exact copy (rescue).
// ============================================================================
__global__ void prepW1_kernel(const float* __restrict__ W1s,
                              const float* __restrict__ W1n) {
    int idx = blockIdx.x * 256 + threadIdx.x;   // 32768 total
    int n = idx & (H1_N - 1);
    int k = idx >> 7;
    float w = (k < IN_F) ? W1s[(size_t)k * H1_N + n]
                         : W1n[(size_t)(k - IN_F) * H1_N + n];
    g_W1hi[n * KTOT + k] = tf32r(w);
    g_W1T [n * KTOT + k] = w;
}

// ============================================================================
// Kernel 1a: GATHER — scattered loads + neighbor mean -> exact A panels (g_Aex).
// Low regs, no dyn smem: full occupancy, latency-tolerant. Bitwise-identical
// arithmetic to the validated gather.
// ============================================================================
__global__ void __launch_bounds__(256)
gather_kernel(const float* __restrict__ x, const int* __restrict__ nodes,
              const int* __restrict__ nbr1, const int* __restrict__ nbr2) {
    __shared__ int s_self[128];
    __shared__ int s_nbr[128 * S1_N];

    const int tid = threadIdx.x;
    const int t = blockIdx.y;
    const int blk = blockIdx.x;               // 0..191
    const int typeA = (blk < (B_N / 128));
    const int rowbase = blk * 128;
    const size_t aex = ((size_t)t * NBLK + blk) * (128 * KTOT);

    if (typeA) {
        if (tid < 128) s_self[tid] = nodes[rowbase + tid];
        for (int q = tid; q < 128 * S1_N; q += 256) {
            int r = q / S1_N, s = q - r * S1_N;
            s_nbr[q] = nbr1[((size_t)t * B_N + rowbase + r) * S1_N + s];
        }
    } else {
        const int j0 = rowbase - B_N;
        if (tid < 128) s_self[tid] = nbr1[(size_t)t * B_N * S1_N + j0 + tid];
        for (int q = tid; q < 128 * S2_N; q += 256) {
            int r = q >> 1, s = q & 1;
            s_nbr[q] = nbr2[((size_t)t * (B_N * S1_N) + j0 + r) * S2_N + s];
        }
    }
    __syncthreads();

    const float* xt = x + (size_t)t * NNODES * IN_F;
    const int gr = tid >> 1;                  // row 0..127
    const int gq = (tid & 1) * 4;             // first of 4 float4 quads per 32-chunk
    float* arow = g_Aex + aex + (size_t)gr * KTOT;

    // self features: k [0,128)
    {
        const float* src = xt + (size_t)s_self[gr] * IN_F;
        #pragma unroll
        for (int kc = 0; kc < 4; kc++) {
            #pragma unroll
            for (int i = 0; i < 4; i++) {
                int f = kc * 32 + (gq + i) * 4;
                float4 v = *(const float4*)(src + f);
                __stcs((float4*)(arow + f), v);
            }
        }
    }
    // neighbor-mean features: k [128,256)
    const int   S    = typeA ? S1_N : S2_N;
    const float invS = typeA ? 0.2f : 0.5f;
    #pragma unroll
    for (int kc = 0; kc < 4; kc++) {
        #pragma unroll
        for (int i = 0; i < 4; i++) {
            int f = kc * 32 + (gq + i) * 4;
            float ax = 0.f, ay = 0.f, az = 0.f, aw = 0.f;
            for (int s = 0; s < S; s++) {
                float4 v = *(const float4*)(xt + (size_t)s_nbr[gr * S + s] * IN_F + f);
                ax += v.x; ay += v.y; az += v.z; aw += v.w;
            }
            __stcs((float4*)(arow + IN_F + f),
                   make_float4(ax * invS, ay * invS, az * invS, aw * invS));
        }
    }
}

// ============================================================================
// Kernel 1b: GEMM — 512-thread CTAs, warp tile 16x64, single-pass tf32 mma.sync
// over g_Aex + spike. Halved per-thread state (acc 32 regs) -> 2 CTAs/SM =
// 32 warps/SM. Same MMA order per output element as R13-R15 (bitwise equal).
// ============================================================================
__global__ void __launch_bounds__(512, 2)
gemm_kernel(const float* __restrict__ b1) {
    extern __shared__ float sm[];
    __shared__ float s_thr[128];

    const int tid = threadIdx.x;
    const int wid = tid >> 5;                 // 0..15
    const int lane = tid & 31;
    const int t = blockIdx.y;
    const int blk = blockIdx.x;               // 0..191
    const int rowbase = blk * 128;
    const size_t aex = ((size_t)t * NBLK + blk) * (128 * KTOT);

    if (tid < 128) s_thr[tid] = 1.0f - b1[tid];

    // staging: 512 threads, 2 quads each (chunk = 128 rows x 32 floats)
    const int gr = tid >> 2;                  // row / n index 0..127
    const int gq = (tid & 3) * 2;             // first of 2 float4 quads

    // warp tile 16x64: 8 M-groups x 2 N-groups
    const int mbase = (wid & 7) * 16;
    const int nbase = (wid >> 3) * 64;
    const int g  = lane >> 2;                 // 0..7
    const int tg = lane & 3;                  // 0..3

    float acc[8][4];
    #pragma unroll
    for (int j = 0; j < 8; j++)
        #pragma unroll
        for (int c = 0; c < 4; c++) acc[j][c] = 0.0f;

    float4 av[2];    // exact A values for staged chunk
    float4 bv[2];    // tf32-pre-rounded B values for staged chunk

    auto load_chunk = [&](int kc) {
        const float* sa = g_Aex + aex + (size_t)gr * KTOT + kc * 32;
        const float* sh = g_W1hi + (size_t)gr * KTOT + kc * 32;
        #pragma unroll
        for (int i = 0; i < 2; i++) {
            av[i] = *(const float4*)(sa + (gq + i) * 4);
            bv[i] = *(const float4*)(sh + (gq + i) * 4);
        }
    };
    auto store_chunk = [&](int b) {
        float* Ah = sm + b * BUFF;
        float* Bh = Ah + 128 * APAD;
        #pragma unroll
        for (int i = 0; i < 2; i++) {
            int o = gr * APAD + (gq + i) * 4;
            *(float4*)(Ah + o) = make_float4(tf32r(av[i].x), tf32r(av[i].y),
                                             tf32r(av[i].z), tf32r(av[i].w));
            *(float4*)(Bh + o) = bv[i];
        }
    };

    load_chunk(0);
    store_chunk(0);

    for (int kc = 0; kc < 8; kc++) {
        __syncthreads();   // buffer (kc&1) visible
        if (kc < 7) load_chunk(kc + 1);       // dense LDGs in flight during MMAs

        const uint32_t* Ah_u = (const uint32_t*)(sm + (kc & 1) * BUFF);
        const uint32_t* Bh_u = Ah_u + 128 * APAD;
        #pragma unroll
        for (int k8 = 0; k8 < 4; k8++) {
            const int kb = k8 * 8;
            uint32_t ah[4];
            {
                int r0 = (mbase + g) * APAD + kb + tg;
                int r8 = r0 + 8 * APAD;
                ah[0] = Ah_u[r0];     ah[1] = Ah_u[r8];
                ah[2] = Ah_u[r0 + 4]; ah[3] = Ah_u[r8 + 4];
            }
            #pragma unroll
            for (int j = 0; j < 8; j++) {
                int bi = (nbase + 8 * j + g) * APAD + kb + tg;
                uint32_t bh0 = Bh_u[bi], bh1 = Bh_u[bi + 4];
                MMA_TF32(acc[j], ah, bh0, bh1);
            }
        }

        if (kc < 7) store_chunk((kc + 1) & 1);
    }

    // ---- epilogue: threshold (+ exact rescue) -> byte-stage -> coalesced store ----
    __syncthreads();
    uint8_t* sbytes = (uint8_t*)sm;           // reuse buffer-0 Ah region (16 KB)
    {
        int R0 = mbase + g;
        #pragma unroll
        for (int j = 0; j < 8; j++) {
            int C0 = nbase + 8 * j + 2 * tg;
            #pragma unroll
            for (int c = 0; c < 4; c++) {
                int R = R0 + (c >> 1) * 8;
                int C = C0 + (c & 1);
                float thr = s_thr[C];
                float d = acc[j][c] - thr;
                bool sp;
                if (fabsf(d) < EPS_RESCUE) {
                    sp = rescue_dot(g_Aex + aex + (size_t)R * KTOT,
                                    g_W1T + (size_t)C * KTOT, thr);
                } else {
                    sp = (d >= 0.0f);
                }
                sbytes[R * 128 + C] = sp ? 1 : 0;
            }
        }
    }
    __syncthreads();
    uint8_t* dst = g_s1 + ((size_t)t * R1 + rowbase) * H1_N;
    #pragma unroll
    for (int i = 0; i < 2; i++) {
        int o = (tid + i * 512) * 16;
        *(uint4*)(dst + o) = *(const uint4*)(sbytes + o);
    }
}

// ============================================================================
// Kernel 2: layer-2 GEMM, packed fp32x2, W streamed from L1 (no smem staging).
// ============================================================================
__global__ void __launch_bounds__(256, 2)
layer2_kernel(const float* __restrict__ W2s, const float* __restrict__ W2n,
              const float* __restrict__ b2) {
    extern __shared__ float sm[];
    float* Zt = sm;                  // [256][64] k-major
    const int tid = threadIdx.x;
    const int t = blockIdx.y;
    const int b0 = blockIdx.x * 64;

    const uint8_t* s1t = g_s1 + (size_t)t * R1 * H1_N;
    const int r  = tid & 63;
    const int w0 = tid >> 6;
    for (int w = w0; w < 32; w += 4) {
        uint32_t gw = *(const uint32_t*)(s1t + (size_t)(b0 + r) * H1_N + w * 4);
        uint32_t mw = 0;   // bytes are 0/1; sum of 5 fits in a byte
        #pragma unroll
        for (int s = 0; s < S1_N; s++)
            mw += *(const uint32_t*)(s1t + (size_t)(B_N + (b0 + r) * S1_N + s) * H1_N + w * 4);
        int k = w * 4;
        Zt[(k + 0) * 64 + r] = (float)(gw & 0xffu);
        Zt[(k + 1) * 64 + r] = (float)((gw >> 8) & 0xffu);
        Zt[(k + 2) * 64 + r] = (float)((gw >> 16) & 0xffu);
        Zt[(k + 3) * 64 + r] = (float)(gw >> 24);
        Zt[(H1_N + k + 0) * 64 + r] = 0.2f * (float)(mw & 0xffu);
        Zt[(H1_N + k + 1) * 64 + r] = 0.2f * (float)((mw >> 8) & 0xffu);
        Zt[(H1_N + k + 2) * 64 + r] = 0.2f * (float)((mw >> 16) & 0xffu);
        Zt[(H1_N + k + 3) * 64 + r] = 0.2f * (float)(mw >> 24);
    }
    __syncthreads();

    const int r0 = (tid & 15) * 4;
    const int c0 = (tid >> 4) * 4;

    ull acc[2][4];
    #pragma unroll
    for (int i = 0; i < 2; i++)
        #pragma unroll
        for (int j = 0; j < 4; j++) acc[i][j] = 0ull;

    // k in [0,128): W2s ; k in [128,256): W2n — same order (bit-identical spikes)
    #pragma unroll
    for (int h = 0; h < 2; h++) {
        const float* Wp = h ? W2n : W2s;
        const int kofs = h * H1_N;
        #pragma unroll 8
        for (int k = 0; k < 128; k++) {
            const ull* za = (const ull*)&Zt[(kofs + k) * 64 + r0];
            ull a0 = za[0], a1 = za[1];
            float4 b4 = *(const float4*)(Wp + (size_t)k * H2_N + c0);
            ull bd0 = dup2(b4.x), bd1 = dup2(b4.y), bd2 = dup2(b4.z), bd3 = dup2(b4.w);
            acc[0][0] = fma2(a0, bd0, acc[0][0]);
            acc[1][0] = fma2(a1, bd0, acc[1][0]);
            acc[0][1] = fma2(a0, bd1, acc[0][1]);
            acc[1][1] = fma2(a1, bd1, acc[1][1]);
            acc[0][2] = fma2(a0, bd2, acc[0][2]);
            acc[1][2] = fma2(a1, bd2, acc[1][2]);
            acc[0][3] = fma2(a0, bd3, acc[0][3]);
            acc[1][3] = fma2(a1, bd3, acc[1][3]);
        }
    }

    float bb[4];
    #pragma unroll
    for (int j = 0; j < 4; j++) bb[j] = b2[c0 + j];
    #pragma unroll
    for (int i = 0; i < 2; i++) {
        int b = b0 + r0 + 2 * i;
        uint32_t pk0 = 0, pk1 = 0;
        #pragma unroll
        for (int j = 0; j < 4; j++) {
            if (lo2(acc[i][j]) + bb[j] >= 1.0f) pk0 |= (1u << (8 * j));
            if (hi2(acc[i][j]) + bb[j] >= 1.0f) pk1 |= (1u << (8 * j));
        }
        *(uint32_t*)(g_s2 + ((size_t)t * B_N + b)     * H2_N + c0) = pk0;
        *(uint32_t*)(g_s2 + ((size_t)t * B_N + b + 1) * H2_N + c0) = pk1;
    }
}

// ============================================================================
// Kernel 3: readout. out[b,j] = ro_b[j] + sum_c (sum_t s2[t,b,c]*A[c,t]) ro_W[c,j]
// ============================================================================
__global__ void __launch_bounds__(256)
readout_kernel(const float* __restrict__ ro_W, const float* __restrict__ ro_b,
               float* __restrict__ out) {
    __shared__ float Msm[8][64];
    const int warp = threadIdx.x >> 5;
    const int lane = threadIdx.x & 31;
    const int b = blockIdx.x * 8 + warp;

    float m0 = 0.f, m1 = 0.f;
    #pragma unroll
    for (int t = 0; t < T_STEPS; t++) {
        const uint8_t* row = g_s2 + ((size_t)t * B_N + b) * H2_N;
        m0 = fmaf((float)row[lane],      g_A[lane * T_STEPS + t],        m0);
        m1 = fmaf((float)row[lane + 32], g_A[(lane + 32) * T_STEPS + t], m1);
    }
    Msm[warp][lane] = m0;
    Msm[warp][lane + 32] = m1;
    __syncwarp();

    float o = ro_b[lane];
    #pragma unroll
    for (int c = 0; c < 64; c++)
        o = fmaf(Msm[warp][c], ro_W[c * C_OUT + lane], o);
    out[(size_t)b * C_OUT + lane] = o;
}

// ============================================================================
extern "C" void kernel_launch(void* const* d_in, const int* in_sizes, int n_in,
                              void* d_out, int out_size) {
    const float* x    = (const float*)d_in[0];
    const int*   nodes= (const int*)  d_in[1];
    const int*   nbr1 = (const int*)  d_in[2];
    const int*   nbr2 = (const int*)  d_in[3];
    const float* W1s  = (const float*)d_in[4];
    const float* W1n  = (const float*)d_in[5];
    const float* b1   = (const float*)d_in[6];
    const float* W2s  = (const float*)d_in[7];
    const float* W2n  = (const float*)d_in[8];
    const float* b2   = (const float*)d_in[9];
    const float* dlw  = (const float*)d_in[10];
    const float* dwk  = (const float*)d_in[11];
    const float* roW  = (const float*)d_in[12];
    const float* rob  = (const float*)d_in[13];
    float* out = (float*)d_out;

    const int l1_smem = 2 * BUFF * 4;   // 90112 B (double-buffered)
    cudaFuncSetAttribute(gemm_kernel, cudaFuncAttributeMaxDynamicSharedMemorySize, l1_smem);
    cudaFuncSetAttribute(layer2_kernel, cudaFuncAttributeMaxDynamicSharedMemorySize, 65536);

    prepA_kernel<<<1, 64>>>(dlw, dwk);
    prepW1_kernel<<<128, 256>>>(W1s, W1n);
    gather_kernel<<<dim3(NBLK, T_STEPS), 256>>>(x, nodes, nbr1, nbr2);
    gemm_kernel<<<dim3(NBLK, T_STEPS), 512, l1_smem>>>(b1);
    layer2_kernel<<<dim3(B_N / 64, T_STEPS), 256, 65536>>>(W2s, W2n, b2);
    readout_kernel<<<B_N / 8, 256>>>(roW, rob, out);
}